// round 8
// baseline (speedup 1.0000x reference)
#include <cuda_runtime.h>
#include <cuda_bf16.h>
#include <stdint.h>
#include <math.h>

#define IN_DIM 64
#define HID    128
#define OUTD   128
#define ETILE  256          // edges per CTA-tile (32 per warp)
#define MAXN   100000

// ------------------------- scratch (no-alloc rule) --------------------------
__device__ float g_src_proj[(size_t)MAXN * HID];
__device__ float g_dst_proj[(size_t)MAXN * HID];

// ------------------------- helpers ------------------------------------------
__device__ __forceinline__ uint32_t smem_u32(const void* p) {
    uint32_t a;
    asm("{ .reg .u64 t; cvta.to.shared.u64 t, %1; cvt.u32.u64 %0, t; }" : "=r"(a) : "l"(p));
    return a;
}
__device__ __forceinline__ void ldsm4(uint32_t* r, uint32_t addr) {
    asm volatile("ldmatrix.sync.aligned.m8n8.x4.shared.b16 {%0,%1,%2,%3}, [%4];"
                 : "=r"(r[0]), "=r"(r[1]), "=r"(r[2]), "=r"(r[3]) : "r"(addr));
}
__device__ __forceinline__ void mma16816(float* d, const uint32_t* a, const uint32_t* b) {
    asm volatile("mma.sync.aligned.m16n8k16.row.col.f32.bf16.bf16.f32 "
                 "{%0,%1,%2,%3}, {%4,%5,%6,%7}, {%8,%9}, {%0,%1,%2,%3};"
                 : "+f"(d[0]), "+f"(d[1]), "+f"(d[2]), "+f"(d[3])
                 : "r"(a[0]), "r"(a[1]), "r"(a[2]), "r"(a[3]), "r"(b[0]), "r"(b[1]));
}
__device__ __forceinline__ void mma_tf32(float* d, const uint32_t* a, uint32_t b0, uint32_t b1) {
    asm volatile("mma.sync.aligned.m16n8k8.row.col.f32.tf32.tf32.f32 "
                 "{%0,%1,%2,%3}, {%4,%5,%6,%7}, {%8,%9}, {%0,%1,%2,%3};"
                 : "+f"(d[0]), "+f"(d[1]), "+f"(d[2]), "+f"(d[3])
                 : "r"(a[0]), "r"(a[1]), "r"(a[2]), "r"(a[3]), "r"(b0), "r"(b1));
}
__device__ __forceinline__ uint32_t cvt_tf32(float f) {
    uint32_t u;
    asm("cvt.rna.tf32.f32 %0, %1;" : "=r"(u) : "f"(f));
    return u;
}
__device__ __forceinline__ void split_pack(float x, float y, uint32_t& h, uint32_t& l) {
    __nv_bfloat16 xh = __float2bfloat16(x), yh = __float2bfloat16(y);
    __nv_bfloat16 xl = __float2bfloat16(x - __bfloat162float(xh));
    __nv_bfloat16 yl = __float2bfloat16(y - __bfloat162float(yh));
    h = (uint32_t)(*(uint16_t*)&xh) | ((uint32_t)(*(uint16_t*)&yh) << 16);
    l = (uint32_t)(*(uint16_t*)&xl) | ((uint32_t)(*(uint16_t*)&yl) << 16);
}
__device__ __forceinline__ float fsilu(float x) { return x / (1.0f + __expf(-x)); }

// ------------------------- smem layouts --------------------------------------
#define OFF_F1 0          // 2048 uint4 : [nt(16)][s2(4)][lane(32)]
#define OFF_F2 32768      // 4096 uint4 : [nt(16)][s2(8)][lane(32)]
#define OFF_ST 98304      // 8192 float2: stash [j2(32)][tid(256)]
#define OFF_BO 163840
#define OFF_GA 164352
#define OFF_BE 164864
#define SMEM_EDGE_BYTES 165376
// node kernel (bf16 3-term)
#define W1_STRIDE 72
#define OFF_NSH 0
#define OFF_NSL 18432
#define OFF_NDH 36864
#define OFF_NDL 55296
#define OFF_NB1 73728
#define SMEM_NODE_BYTES 74240

__device__ __forceinline__ void stage_w64(const float* __restrict__ W,
                                          __nv_bfloat16* sH, __nv_bfloat16* sL, int tid, int nthr) {
    for (int i = tid; i < HID * (IN_DIM / 2); i += nthr) {
        int n = i >> 5, p = i & 31;
        float2 f = ((const float2*)W)[n * 32 + p];
        __nv_bfloat16 xh = __float2bfloat16(f.x), yh = __float2bfloat16(f.y);
        sH[n * W1_STRIDE + 2 * p]     = xh;
        sH[n * W1_STRIDE + 2 * p + 1] = yh;
        sL[n * W1_STRIDE + 2 * p]     = __float2bfloat16(f.x - __bfloat162float(xh));
        sL[n * W1_STRIDE + 2 * p + 1] = __float2bfloat16(f.y - __bfloat162float(yh));
    }
}

// ---------------------------------------------------------------------------
// Kernel 1: node projections via HMMA bf16 3-term (near-exact) — unchanged
// ---------------------------------------------------------------------------
__global__ __launch_bounds__(256) void node_mma_kernel(
    const float* __restrict__ src_feat, const float* __restrict__ dst_feat,
    const float* __restrict__ W_src, const float* __restrict__ W_dst,
    const float* __restrict__ b1, int Nn, int ntilesN)
{
    extern __shared__ char smraw[];
    char* sm = smraw;
    const uint32_t base = smem_u32(smraw);
    const int tid = threadIdx.x;

    stage_w64(W_src, (__nv_bfloat16*)(sm + OFF_NSH), (__nv_bfloat16*)(sm + OFF_NSL), tid, 256);
    stage_w64(W_dst, (__nv_bfloat16*)(sm + OFF_NDH), (__nv_bfloat16*)(sm + OFF_NDL), tid, 256);
    if (tid < 128) ((float*)(sm + OFF_NB1))[tid] = b1[tid];
    __syncthreads();

    const int lane = tid & 31, warp = tid >> 5;
    const int qrow = lane >> 2, qcol = lane & 3;
    const int g = lane >> 3, r = lane & 7;
    const int lro = ((g & 2) ? 8 : 0) + r;
    const int lco = (g & 1) * 8;
    const uint32_t lmoff = (uint32_t)(lro * W1_STRIDE + lco) * 2;

    const int nitems = 2 * ntilesN;
    for (int item = blockIdx.x; item < nitems; item += gridDim.x) {
        const bool is_dst = (item >= ntilesN);
        const int tile = is_dst ? (item - ntilesN) : item;
        const float* X = is_dst ? dst_feat : src_feat;
        float* Out = is_dst ? g_dst_proj : g_src_proj;
        const uint32_t wh_base = base + (is_dst ? OFF_NDH : OFF_NSH) + lmoff;
        const uint32_t wl_base = base + (is_dst ? OFF_NDL : OFF_NSL) + lmoff;

        const int n0w = tile * 128 + warp * 16;
        const int nr0i = n0w + qrow, nr1i = nr0i + 8;
        const int gn0 = (nr0i < Nn) ? nr0i : (Nn - 1);
        const int gn1 = (nr1i < Nn) ? nr1i : (Nn - 1);
        const float* xr0 = X + (size_t)gn0 * IN_DIM + 2 * qcol;
        const float* xr1 = X + (size_t)gn1 * IN_DIM + 2 * qcol;

        uint32_t aH[4][4], aL[4][4];
        #pragma unroll
        for (int s = 0; s < 4; s++) {
            float2 f0 = *(const float2*)(xr0 + 16 * s);
            float2 f1 = *(const float2*)(xr1 + 16 * s);
            float2 f2 = *(const float2*)(xr0 + 16 * s + 8);
            float2 f3 = *(const float2*)(xr1 + 16 * s + 8);
            split_pack(f0.x, f0.y, aH[s][0], aL[s][0]);
            split_pack(f1.x, f1.y, aH[s][1], aL[s][1]);
            split_pack(f2.x, f2.y, aH[s][2], aL[s][2]);
            split_pack(f3.x, f3.y, aH[s][3], aL[s][3]);
        }

        float acc[16][4];
        #pragma unroll
        for (int j = 0; j < 16; j++) { acc[j][0]=0.f; acc[j][1]=0.f; acc[j][2]=0.f; acc[j][3]=0.f; }

        #pragma unroll
        for (int s = 0; s < 4; s++) {
            uint32_t bH[8][4], bL[8][4];
            #pragma unroll
            for (int jp = 0; jp < 8; jp++)
                ldsm4(bH[jp], wh_base + (uint32_t)(jp * 16 * W1_STRIDE + 16 * s) * 2);
            #pragma unroll
            for (int jp = 0; jp < 8; jp++) {
                mma16816(acc[2*jp],   aH[s], bH[jp]);
                mma16816(acc[2*jp+1], aH[s], bH[jp] + 2);
            }
            #pragma unroll
            for (int jp = 0; jp < 8; jp++)
                ldsm4(bL[jp], wl_base + (uint32_t)(jp * 16 * W1_STRIDE + 16 * s) * 2);
            #pragma unroll
            for (int jp = 0; jp < 8; jp++) {
                mma16816(acc[2*jp],   aL[s], bH[jp]);
                mma16816(acc[2*jp+1], aL[s], bH[jp] + 2);
            }
            #pragma unroll
            for (int jp = 0; jp < 8; jp++) {
                mma16816(acc[2*jp],   aH[s], bL[jp]);
                mma16816(acc[2*jp+1], aH[s], bL[jp] + 2);
            }
        }

        const float* sb1 = (const float*)(sm + OFF_NB1);
        const bool st0 = (nr0i < Nn), st1 = (nr1i < Nn);
        float* o0 = Out + (size_t)nr0i * HID + 2 * qcol;
        float* o1 = Out + (size_t)nr1i * HID + 2 * qcol;
        #pragma unroll
        for (int j = 0; j < 16; j++) {
            float2 bb = make_float2(0.f, 0.f);
            if (is_dst) bb = *(const float2*)(sb1 + 8 * j + 2 * qcol);
            if (st0) *(float2*)(o0 + 8 * j) = make_float2(acc[j][0] + bb.x, acc[j][1] + bb.y);
            if (st1) *(float2*)(o1 + 8 * j) = make_float2(acc[j][2] + bb.x, acc[j][3] + bb.y);
        }
    }
}

// ---------------------------------------------------------------------------
// Kernel 2: persistent TF32 edge pipeline, M=32 per warp (B frags shared by
// two m16 blocks), GEMM2 split in two n-halves with smem stash for half 1.
// ---------------------------------------------------------------------------
__global__ __launch_bounds__(256) void edge_tf32_kernel(
    const float* __restrict__ efeat,
    const int* __restrict__ src_idx, const int* __restrict__ dst_idx,
    const float* __restrict__ W_efeat, const float* __restrict__ W_out,
    const float* __restrict__ b_out, const float* __restrict__ gamma,
    const float* __restrict__ beta,
    float* __restrict__ out, int E, int ntiles)
{
    extern __shared__ char smraw[];
    char* sm = smraw;
    const int tid = threadIdx.x;

    // ---- stage W1 frags: [nt(16)][s2(4)][lane(32)]
    {
        uint4* f1s = (uint4*)(sm + OFF_F1);
        for (int idx = tid; idx < 2048; idx += 256) {
            int nt = idx >> 7, rem = idx & 127;
            int s2 = rem >> 5, l = rem & 31;
            int q = l & 3, gp = l >> 2;
            int Ln = (gp >> 1) * 32 + 2 * nt + (gp & 1);
            int col = q * 16 + 4 * s2;
            float4 w = *(const float4*)(W_efeat + Ln * IN_DIM + col);
            f1s[idx] = make_uint4(cvt_tf32(w.x), cvt_tf32(w.y), cvt_tf32(w.z), cvt_tf32(w.w));
        }
    }
    // ---- stage W2 frags: [nt(16)][s2(8)][lane(32)]
    {
        uint4* f2s = (uint4*)(sm + OFF_F2);
        for (int idx = tid; idx < 4096; idx += 256) {
            int nt = idx >> 8, rem = idx & 255;
            int s2 = rem >> 5, l = rem & 31;
            int q = l & 3, gp = l >> 2;
            int n = nt * 8 + gp;
            int col = q * 32 + 4 * s2;
            float4 w = *(const float4*)(W_out + n * HID + col);
            f2s[idx] = make_uint4(cvt_tf32(w.x), cvt_tf32(w.y), cvt_tf32(w.z), cvt_tf32(w.w));
        }
    }
    if (tid < 128) {
        ((float*)(sm + OFF_BO))[tid] = b_out[tid];
        ((float*)(sm + OFF_GA))[tid] = gamma[tid];
        ((float*)(sm + OFF_BE))[tid] = beta[tid];
    }
    __syncthreads();

    const float* sBO = (const float*)(sm + OFF_BO);
    const float* sGA = (const float*)(sm + OFF_GA);
    const float* sBE = (const float*)(sm + OFF_BE);
    const uint4* f1 = (const uint4*)(sm + OFF_F1);
    const uint4* f2 = (const uint4*)(sm + OFF_F2);
    float2* sST = (float2*)(sm + OFF_ST);    // [j2(32)][tid(256)]

    const int lane = tid & 31, warp = tid >> 5;
    const int qrow = lane >> 2, qcol = lane & 3;

    for (int tile = blockIdx.x; tile < ntiles; tile += gridDim.x) {
        const int e0w = tile * ETILE + warp * 32;
        // 4 edge rows per thread: block b in {0,1}, sub-row h in {0,1}
        int rr[2][2];
        rr[0][0] = e0w + qrow;      rr[0][1] = rr[0][0] + 8;
        rr[1][0] = e0w + 16 + qrow; rr[1][1] = rr[1][0] + 8;
        int gg[2][2];
        #pragma unroll
        for (int b = 0; b < 2; b++)
            #pragma unroll
            for (int h = 0; h < 2; h++)
                gg[b][h] = (rr[b][h] < E) ? rr[b][h] : (E - 1);

        int si[2][2], di[2][2];
        #pragma unroll
        for (int b = 0; b < 2; b++)
            #pragma unroll
            for (int h = 0; h < 2; h++) {
                si[b][h] = src_idx[gg[b][h]];
                di[b][h] = dst_idx[gg[b][h]];
                asm volatile("prefetch.global.L2 [%0];"
                             :: "l"(g_src_proj + (size_t)si[b][h] * HID + qcol * 32));
                asm volatile("prefetch.global.L2 [%0];"
                             :: "l"(g_dst_proj + (size_t)di[b][h] * HID + qcol * 32));
            }

        // ---- A1 frags (psi permutation: 16 contiguous floats per row) ----
        uint32_t a1[2][8][4];
        #pragma unroll
        for (int b = 0; b < 2; b++) {
            const float4* e0p = (const float4*)(efeat + (size_t)gg[b][0] * IN_DIM + qcol * 16);
            const float4* e1p = (const float4*)(efeat + (size_t)gg[b][1] * IN_DIM + qcol * 16);
            #pragma unroll
            for (int t = 0; t < 4; t++) {
                float4 v0 = e0p[t], v1 = e1p[t];
                a1[b][2*t][0]   = cvt_tf32(v0.x); a1[b][2*t][2]   = cvt_tf32(v0.y);
                a1[b][2*t][1]   = cvt_tf32(v1.x); a1[b][2*t][3]   = cvt_tf32(v1.y);
                a1[b][2*t+1][0] = cvt_tf32(v0.z); a1[b][2*t+1][2] = cvt_tf32(v0.w);
                a1[b][2*t+1][1] = cvt_tf32(v1.z); a1[b][2*t+1][3] = cvt_tf32(v1.w);
            }
        }

        // ---- GEMM1: 2 x (32x128x64) tf32, B frags shared across blocks ----
        float acc1[2][16][4];
        #pragma unroll
        for (int b = 0; b < 2; b++)
            #pragma unroll
            for (int j = 0; j < 16; j++) {
                acc1[b][j][0]=0.f; acc1[b][j][1]=0.f; acc1[b][j][2]=0.f; acc1[b][j][3]=0.f;
            }
        #pragma unroll
        for (int s2 = 0; s2 < 4; s2++) {
            #pragma unroll
            for (int ntg = 0; ntg < 4; ntg++) {
                const int n0 = 4 * ntg;
                uint4 bf[4];
                #pragma unroll
                for (int i = 0; i < 4; i++)
                    bf[i] = f1[((n0 + i) * 4 + s2) * 32 + lane];
                #pragma unroll
                for (int i = 0; i < 4; i++) {
                    mma_tf32(acc1[0][n0+i], a1[0][2*s2],   bf[i].x, bf[i].y);
                    mma_tf32(acc1[1][n0+i], a1[1][2*s2],   bf[i].x, bf[i].y);
                    mma_tf32(acc1[0][n0+i], a1[0][2*s2+1], bf[i].z, bf[i].w);
                    mma_tf32(acc1[1][n0+i], a1[1][2*s2+1], bf[i].z, bf[i].w);
                }
            }
        }

        // ---- gather + SiLU + cvt -> GEMM2 A frags (acc1 dies) ----
        uint32_t a2[2][16][4];
        #pragma unroll
        for (int b = 0; b < 2; b++) {
            const float4* ps0 = (const float4*)(g_src_proj + (size_t)si[b][0] * HID + qcol * 32);
            const float4* pd0 = (const float4*)(g_dst_proj + (size_t)di[b][0] * HID + qcol * 32);
            const float4* ps1 = (const float4*)(g_src_proj + (size_t)si[b][1] * HID + qcol * 32);
            const float4* pd1 = (const float4*)(g_dst_proj + (size_t)di[b][1] * HID + qcol * 32);
            #pragma unroll
            for (int ntp = 0; ntp < 8; ntp++) {
                float4 gs0 = ps0[ntp], gd0 = pd0[ntp];
                float4 gs1 = ps1[ntp], gd1 = pd1[ntp];
                {
                    const int nt = 2 * ntp;
                    float v0 = fsilu(acc1[b][nt][0] + gs0.x + gd0.x);
                    float v1 = fsilu(acc1[b][nt][1] + gs0.y + gd0.y);
                    float v2 = fsilu(acc1[b][nt][2] + gs1.x + gd1.x);
                    float v3 = fsilu(acc1[b][nt][3] + gs1.y + gd1.y);
                    a2[b][nt][0] = cvt_tf32(v0); a2[b][nt][2] = cvt_tf32(v1);
                    a2[b][nt][1] = cvt_tf32(v2); a2[b][nt][3] = cvt_tf32(v3);
                }
                {
                    const int nt = 2 * ntp + 1;
                    float v0 = fsilu(acc1[b][nt][0] + gs0.z + gd0.z);
                    float v1 = fsilu(acc1[b][nt][1] + gs0.w + gd0.w);
                    float v2 = fsilu(acc1[b][nt][2] + gs1.z + gd1.z);
                    float v3 = fsilu(acc1[b][nt][3] + gs1.w + gd1.w);
                    a2[b][nt][0] = cvt_tf32(v0); a2[b][nt][2] = cvt_tf32(v1);
                    a2[b][nt][1] = cvt_tf32(v2); a2[b][nt][3] = cvt_tf32(v3);
                }
            }
        }

        float sS[2][2]  = {{0.f, 0.f}, {0.f, 0.f}};
        float sQ[2][2]  = {{0.f, 0.f}, {0.f, 0.f}};

        // ---- GEMM2 half 1 (output n-tiles 0..7) -> bias, stats, stash ----
        {
            float acc2[2][8][4];
            #pragma unroll
            for (int b = 0; b < 2; b++)
                #pragma unroll
                for (int j = 0; j < 8; j++) {
                    acc2[b][j][0]=0.f; acc2[b][j][1]=0.f; acc2[b][j][2]=0.f; acc2[b][j][3]=0.f;
                }
            #pragma unroll
            for (int s2 = 0; s2 < 8; s2++) {
                #pragma unroll
                for (int ntg = 0; ntg < 2; ntg++) {
                    const int n0 = 4 * ntg;
                    uint4 bf[4];
                    #pragma unroll
                    for (int i = 0; i < 4; i++)
                        bf[i] = f2[((n0 + i) * 8 + s2) * 32 + lane];
                    #pragma unroll
                    for (int i = 0; i < 4; i++) {
                        mma_tf32(acc2[0][n0+i], a2[0][2*s2],   bf[i].x, bf[i].y);
                        mma_tf32(acc2[1][n0+i], a2[1][2*s2],   bf[i].x, bf[i].y);
                        mma_tf32(acc2[0][n0+i], a2[0][2*s2+1], bf[i].z, bf[i].w);
                        mma_tf32(acc2[1][n0+i], a2[1][2*s2+1], bf[i].z, bf[i].w);
                    }
                }
            }
            #pragma unroll
            for (int b = 0; b < 2; b++) {
                #pragma unroll
                for (int nt = 0; nt < 8; nt++) {
                    float2 bo = *(const float2*)(sBO + nt * 8 + 2 * qcol);
                    float v0 = acc2[b][nt][0] + bo.x;
                    float v1 = acc2[b][nt][1] + bo.y;
                    float v2 = acc2[b][nt][2] + bo.x;
                    float v3 = acc2[b][nt][3] + bo.y;
                    sS[b][0] += v0 + v1;  sQ[b][0] += v0 * v0 + v1 * v1;
                    sS[b][1] += v2 + v3;  sQ[b][1] += v2 * v2 + v3 * v3;
                    sST[(b * 16 + nt * 2 + 0) * 256 + tid] = make_float2(v0, v1);
                    sST[(b * 16 + nt * 2 + 1) * 256 + tid] = make_float2(v2, v3);
                }
            }
        }

        // ---- GEMM2 half 2 (output n-tiles 8..15) ----
        float acc2[2][8][4];
        #pragma unroll
        for (int b = 0; b < 2; b++)
            #pragma unroll
            for (int j = 0; j < 8; j++) {
                acc2[b][j][0]=0.f; acc2[b][j][1]=0.f; acc2[b][j][2]=0.f; acc2[b][j][3]=0.f;
            }
        #pragma unroll
        for (int s2 = 0; s2 < 8; s2++) {
            #pragma unroll
            for (int ntg = 0; ntg < 2; ntg++) {
                const int n0 = 4 * ntg;
                uint4 bf[4];
                #pragma unroll
                for (int i = 0; i < 4; i++)
                    bf[i] = f2[((8 + n0 + i) * 8 + s2) * 32 + lane];
                #pragma unroll
                for (int i = 0; i < 4; i++) {
                    mma_tf32(acc2[0][n0+i], a2[0][2*s2],   bf[i].x, bf[i].y);
                    mma_tf32(acc2[1][n0+i], a2[1][2*s2],   bf[i].x, bf[i].y);
                    mma_tf32(acc2[0][n0+i], a2[0][2*s2+1], bf[i].z, bf[i].w);
                    mma_tf32(acc2[1][n0+i], a2[1][2*s2+1], bf[i].z, bf[i].w);
                }
            }
        }
        #pragma unroll
        for (int b = 0; b < 2; b++) {
            #pragma unroll
            for (int nt = 0; nt < 8; nt++) {
                float2 bo = *(const float2*)(sBO + 64 + nt * 8 + 2 * qcol);
                acc2[b][nt][0] += bo.x; acc2[b][nt][1] += bo.y;
                acc2[b][nt][2] += bo.x; acc2[b][nt][3] += bo.y;
                sS[b][0] += acc2[b][nt][0] + acc2[b][nt][1];
                sQ[b][0] += acc2[b][nt][0] * acc2[b][nt][0] + acc2[b][nt][1] * acc2[b][nt][1];
                sS[b][1] += acc2[b][nt][2] + acc2[b][nt][3];
                sQ[b][1] += acc2[b][nt][2] * acc2[b][nt][2] + acc2[b][nt][3] * acc2[b][nt][3];
            }
        }

        // ---- LN stats (quad shuffle) ----
        float mu[2][2], iv[2][2];
        #pragma unroll
        for (int b = 0; b < 2; b++)
            #pragma unroll
            for (int h = 0; h < 2; h++) {
                float s = sS[b][h], q = sQ[b][h];
                s += __shfl_xor_sync(0xffffffffu, s, 1);  s += __shfl_xor_sync(0xffffffffu, s, 2);
                q += __shfl_xor_sync(0xffffffffu, q, 1);  q += __shfl_xor_sync(0xffffffffu, q, 2);
                float m = s * (1.0f / OUTD);
                float v = q * (1.0f / OUTD) - m * m;
                mu[b][h] = m;
                iv[b][h] = rsqrtf(v + 1e-5f);
            }

        // ---- store half 2 from registers (cols 64..127) ----
        #pragma unroll
        for (int b = 0; b < 2; b++) {
            const bool w0 = (rr[b][0] < E), w1 = (rr[b][1] < E);
            float* o0 = out + (size_t)rr[b][0] * OUTD + 64 + 2 * qcol;
            float* o1 = out + (size_t)rr[b][1] * OUTD + 64 + 2 * qcol;
            #pragma unroll
            for (int nt = 0; nt < 8; nt++) {
                float2 ga = *(const float2*)(sGA + 64 + nt * 8 + 2 * qcol);
                float2 be = *(const float2*)(sBE + 64 + nt * 8 + 2 * qcol);
                if (w0) {
                    float2 w;
                    w.x = (acc2[b][nt][0] - mu[b][0]) * iv[b][0] * ga.x + be.x;
                    w.y = (acc2[b][nt][1] - mu[b][0]) * iv[b][0] * ga.y + be.y;
                    *(float2*)(o0 + nt * 8) = w;
                }
                if (w1) {
                    float2 w;
                    w.x = (acc2[b][nt][2] - mu[b][1]) * iv[b][1] * ga.x + be.x;
                    w.y = (acc2[b][nt][3] - mu[b][1]) * iv[b][1] * ga.y + be.y;
                    *(float2*)(o1 + nt * 8) = w;
                }
            }
        }

        // ---- reload stash, store half 1 (cols 0..63) ----
        #pragma unroll
        for (int b = 0; b < 2; b++) {
            const bool w0 = (rr[b][0] < E), w1 = (rr[b][1] < E);
            float* o0 = out + (size_t)rr[b][0] * OUTD + 2 * qcol;
            float* o1 = out + (size_t)rr[b][1] * OUTD + 2 * qcol;
            #pragma unroll
            for (int nt = 0; nt < 8; nt++) {
                float2 ga = *(const float2*)(sGA + nt * 8 + 2 * qcol);
                float2 be = *(const float2*)(sBE + nt * 8 + 2 * qcol);
                float2 v01 = sST[(b * 16 + nt * 2 + 0) * 256 + tid];
                float2 v23 = sST[(b * 16 + nt * 2 + 1) * 256 + tid];
                if (w0) {
                    float2 w;
                    w.x = (v01.x - mu[b][0]) * iv[b][0] * ga.x + be.x;
                    w.y = (v01.y - mu[b][0]) * iv[b][0] * ga.y + be.y;
                    *(float2*)(o0 + nt * 8) = w;
                }
                if (w1) {
                    float2 w;
                    w.x = (v23.x - mu[b][1]) * iv[b][1] * ga.x + be.x;
                    w.y = (v23.y - mu[b][1]) * iv[b][1] * ga.y + be.y;
                    *(float2*)(o1 + nt * 8) = w;
                }
            }
        }
    }
}

// ---------------------------------------------------------------------------
extern "C" void kernel_launch(void* const* d_in, const int* in_sizes, int n_in,
                              void* d_out, int out_size)
{
    const float* efeat    = (const float*)d_in[0];
    const float* src_feat = (const float*)d_in[1];
    const float* dst_feat = (const float*)d_in[2];
    const int*   src_idx  = (const int*)d_in[3];
    const int*   dst_idx  = (const int*)d_in[4];
    const float* W_efeat  = (const float*)d_in[5];
    const float* W_src    = (const float*)d_in[6];
    const float* W_dst    = (const float*)d_in[7];
    const float* b1       = (const float*)d_in[8];
    const float* W_out    = (const float*)d_in[9];
    const float* b_out    = (const float*)d_in[10];
    const float* ln_gamma = (const float*)d_in[11];
    const float* ln_beta  = (const float*)d_in[12];
    float* out = (float*)d_out;

    const int E  = in_sizes[0] / IN_DIM;
    const int Nn = in_sizes[1] / IN_DIM;
    const int ntiles  = (E + ETILE - 1) / ETILE;
    const int ntilesN = (Nn + 127) / 128;

    cudaFuncSetAttribute(node_mma_kernel, cudaFuncAttributeMaxDynamicSharedMemorySize, SMEM_NODE_BYTES);
    cudaFuncSetAttribute(edge_tf32_kernel, cudaFuncAttributeMaxDynamicSharedMemorySize, SMEM_EDGE_BYTES);

    int nsm = 148;
    cudaDeviceGetAttribute(&nsm, cudaDevAttrMultiProcessorCount, 0);

    int gridN = 2 * ntilesN < nsm ? 2 * ntilesN : nsm;
    node_mma_kernel<<<gridN, 256, SMEM_NODE_BYTES>>>(src_feat, dst_feat, W_src, W_dst, b1, Nn, ntilesN);

    int grid = (ntiles < nsm) ? ntiles : nsm;
    edge_tf32_kernel<<<grid, 256, SMEM_EDGE_BYTES>>>(efeat, src_idx, dst_idx, W_efeat, W_out,
                                                     b_out, ln_gamma, ln_beta, out, E, ntiles);
}

// round 9
// speedup vs baseline: 1.1606x; 1.1606x over previous
#include <cuda_runtime.h>
#include <cuda_bf16.h>
#include <stdint.h>
#include <math.h>

#define IN_DIM 64
#define HID    128
#define OUTD   128
#define ETILE  192          // edges per CTA-tile (12 warps x 16)
#define NTHR   384
#define MAXN   100000

// ------------------------- scratch (no-alloc rule) --------------------------
__device__ float g_src_proj[(size_t)MAXN * HID];
__device__ float g_dst_proj[(size_t)MAXN * HID];

// ------------------------- helpers ------------------------------------------
__device__ __forceinline__ uint32_t smem_u32(const void* p) {
    uint32_t a;
    asm("{ .reg .u64 t; cvta.to.shared.u64 t, %1; cvt.u32.u64 %0, t; }" : "=r"(a) : "l"(p));
    return a;
}
__device__ __forceinline__ void ldsm4(uint32_t* r, uint32_t addr) {
    asm volatile("ldmatrix.sync.aligned.m8n8.x4.shared.b16 {%0,%1,%2,%3}, [%4];"
                 : "=r"(r[0]), "=r"(r[1]), "=r"(r[2]), "=r"(r[3]) : "r"(addr));
}
__device__ __forceinline__ void mma16816(float* d, const uint32_t* a, const uint32_t* b) {
    asm volatile("mma.sync.aligned.m16n8k16.row.col.f32.bf16.bf16.f32 "
                 "{%0,%1,%2,%3}, {%4,%5,%6,%7}, {%8,%9}, {%0,%1,%2,%3};"
                 : "+f"(d[0]), "+f"(d[1]), "+f"(d[2]), "+f"(d[3])
                 : "r"(a[0]), "r"(a[1]), "r"(a[2]), "r"(a[3]), "r"(b[0]), "r"(b[1]));
}
__device__ __forceinline__ void mma_tf32(float* d, const uint32_t* a, uint32_t b0, uint32_t b1) {
    asm volatile("mma.sync.aligned.m16n8k8.row.col.f32.tf32.tf32.f32 "
                 "{%0,%1,%2,%3}, {%4,%5,%6,%7}, {%8,%9}, {%0,%1,%2,%3};"
                 : "+f"(d[0]), "+f"(d[1]), "+f"(d[2]), "+f"(d[3])
                 : "r"(a[0]), "r"(a[1]), "r"(a[2]), "r"(a[3]), "r"(b0), "r"(b1));
}
__device__ __forceinline__ uint32_t cvt_tf32(float f) {
    uint32_t u;
    asm("cvt.rna.tf32.f32 %0, %1;" : "=r"(u) : "f"(f));
    return u;
}
__device__ __forceinline__ void split_pack(float x, float y, uint32_t& h, uint32_t& l) {
    __nv_bfloat16 xh = __float2bfloat16(x), yh = __float2bfloat16(y);
    __nv_bfloat16 xl = __float2bfloat16(x - __bfloat162float(xh));
    __nv_bfloat16 yl = __float2bfloat16(y - __bfloat162float(yh));
    h = (uint32_t)(*(uint16_t*)&xh) | ((uint32_t)(*(uint16_t*)&yh) << 16);
    l = (uint32_t)(*(uint16_t*)&xl) | ((uint32_t)(*(uint16_t*)&yl) << 16);
}
__device__ __forceinline__ float fsilu(float x) { return x / (1.0f + __expf(-x)); }

// ------------------------- smem layouts --------------------------------------
#define OFF_F1 0          // 2048 uint4 : [nt(16)][s2(4)][lane(32)]
#define OFF_F2 32768      // 4096 uint4 : [nt(16)][s2(8)][lane(32)]
#define OFF_BO 98304
#define OFF_GA 98816
#define OFF_BE 99328
#define SMEM_EDGE_BYTES 99840
// node kernel (bf16 3-term)
#define W1_STRIDE 72
#define OFF_NSH 0
#define OFF_NSL 18432
#define OFF_NDH 36864
#define OFF_NDL 55296
#define OFF_NB1 73728
#define SMEM_NODE_BYTES 74240

__device__ __forceinline__ void stage_w64(const float* __restrict__ W,
                                          __nv_bfloat16* sH, __nv_bfloat16* sL, int tid, int nthr) {
    for (int i = tid; i < HID * (IN_DIM / 2); i += nthr) {
        int n = i >> 5, p = i & 31;
        float2 f = ((const float2*)W)[n * 32 + p];
        __nv_bfloat16 xh = __float2bfloat16(f.x), yh = __float2bfloat16(f.y);
        sH[n * W1_STRIDE + 2 * p]     = xh;
        sH[n * W1_STRIDE + 2 * p + 1] = yh;
        sL[n * W1_STRIDE + 2 * p]     = __float2bfloat16(f.x - __bfloat162float(xh));
        sL[n * W1_STRIDE + 2 * p + 1] = __float2bfloat16(f.y - __bfloat162float(yh));
    }
}

// ---------------------------------------------------------------------------
// Kernel 1: node projections via HMMA bf16 3-term (near-exact)
// ---------------------------------------------------------------------------
__global__ __launch_bounds__(256) void node_mma_kernel(
    const float* __restrict__ src_feat, const float* __restrict__ dst_feat,
    const float* __restrict__ W_src, const float* __restrict__ W_dst,
    const float* __restrict__ b1, int Nn, int ntilesN)
{
    extern __shared__ char smraw[];
    char* sm = smraw;
    const uint32_t base = smem_u32(smraw);
    const int tid = threadIdx.x;

    stage_w64(W_src, (__nv_bfloat16*)(sm + OFF_NSH), (__nv_bfloat16*)(sm + OFF_NSL), tid, 256);
    stage_w64(W_dst, (__nv_bfloat16*)(sm + OFF_NDH), (__nv_bfloat16*)(sm + OFF_NDL), tid, 256);
    if (tid < 128) ((float*)(sm + OFF_NB1))[tid] = b1[tid];
    __syncthreads();

    const int lane = tid & 31, warp = tid >> 5;
    const int qrow = lane >> 2, qcol = lane & 3;
    const int g = lane >> 3, r = lane & 7;
    const int lro = ((g & 2) ? 8 : 0) + r;
    const int lco = (g & 1) * 8;
    const uint32_t lmoff = (uint32_t)(lro * W1_STRIDE + lco) * 2;

    const int nitems = 2 * ntilesN;
    for (int item = blockIdx.x; item < nitems; item += gridDim.x) {
        const bool is_dst = (item >= ntilesN);
        const int tile = is_dst ? (item - ntilesN) : item;
        const float* X = is_dst ? dst_feat : src_feat;
        float* Out = is_dst ? g_dst_proj : g_src_proj;
        const uint32_t wh_base = base + (is_dst ? OFF_NDH : OFF_NSH) + lmoff;
        const uint32_t wl_base = base + (is_dst ? OFF_NDL : OFF_NSL) + lmoff;

        const int n0w = tile * 128 + warp * 16;
        const int nr0i = n0w + qrow, nr1i = nr0i + 8;
        const int gn0 = (nr0i < Nn) ? nr0i : (Nn - 1);
        const int gn1 = (nr1i < Nn) ? nr1i : (Nn - 1);
        const float* xr0 = X + (size_t)gn0 * IN_DIM + 2 * qcol;
        const float* xr1 = X + (size_t)gn1 * IN_DIM + 2 * qcol;

        uint32_t aH[4][4], aL[4][4];
        #pragma unroll
        for (int s = 0; s < 4; s++) {
            float2 f0 = *(const float2*)(xr0 + 16 * s);
            float2 f1 = *(const float2*)(xr1 + 16 * s);
            float2 f2 = *(const float2*)(xr0 + 16 * s + 8);
            float2 f3 = *(const float2*)(xr1 + 16 * s + 8);
            split_pack(f0.x, f0.y, aH[s][0], aL[s][0]);
            split_pack(f1.x, f1.y, aH[s][1], aL[s][1]);
            split_pack(f2.x, f2.y, aH[s][2], aL[s][2]);
            split_pack(f3.x, f3.y, aH[s][3], aL[s][3]);
        }

        float acc[16][4];
        #pragma unroll
        for (int j = 0; j < 16; j++) { acc[j][0]=0.f; acc[j][1]=0.f; acc[j][2]=0.f; acc[j][3]=0.f; }

        #pragma unroll
        for (int s = 0; s < 4; s++) {
            uint32_t bH[8][4], bL[8][4];
            #pragma unroll
            for (int jp = 0; jp < 8; jp++)
                ldsm4(bH[jp], wh_base + (uint32_t)(jp * 16 * W1_STRIDE + 16 * s) * 2);
            #pragma unroll
            for (int jp = 0; jp < 8; jp++) {
                mma16816(acc[2*jp],   aH[s], bH[jp]);
                mma16816(acc[2*jp+1], aH[s], bH[jp] + 2);
            }
            #pragma unroll
            for (int jp = 0; jp < 8; jp++)
                ldsm4(bL[jp], wl_base + (uint32_t)(jp * 16 * W1_STRIDE + 16 * s) * 2);
            #pragma unroll
            for (int jp = 0; jp < 8; jp++) {
                mma16816(acc[2*jp],   aL[s], bH[jp]);
                mma16816(acc[2*jp+1], aL[s], bH[jp] + 2);
            }
            #pragma unroll
            for (int jp = 0; jp < 8; jp++) {
                mma16816(acc[2*jp],   aH[s], bL[jp]);
                mma16816(acc[2*jp+1], aH[s], bL[jp] + 2);
            }
        }

        const float* sb1 = (const float*)(sm + OFF_NB1);
        const bool st0 = (nr0i < Nn), st1 = (nr1i < Nn);
        float* o0 = Out + (size_t)nr0i * HID + 2 * qcol;
        float* o1 = Out + (size_t)nr1i * HID + 2 * qcol;
        #pragma unroll
        for (int j = 0; j < 16; j++) {
            float2 bb = make_float2(0.f, 0.f);
            if (is_dst) bb = *(const float2*)(sb1 + 8 * j + 2 * qcol);
            if (st0) *(float2*)(o0 + 8 * j) = make_float2(acc[j][0] + bb.x, acc[j][1] + bb.y);
            if (st1) *(float2*)(o1 + 8 * j) = make_float2(acc[j][2] + bb.x, acc[j][3] + bb.y);
        }
    }
}

// ---------------------------------------------------------------------------
// Kernel 2: persistent TF32 edge pipeline (R7 structure), 384 threads / CTA
// ---------------------------------------------------------------------------
__global__ __launch_bounds__(NTHR, 1) void edge_tf32_kernel(
    const float* __restrict__ efeat,
    const int* __restrict__ src_idx, const int* __restrict__ dst_idx,
    const float* __restrict__ W_efeat, const float* __restrict__ W_out,
    const float* __restrict__ b_out, const float* __restrict__ gamma,
    const float* __restrict__ beta,
    float* __restrict__ out, int E, int ntiles)
{
    extern __shared__ char smraw[];
    char* sm = smraw;
    const int tid = threadIdx.x;

    // ---- stage W1 frags: [nt(16)][s2(4)][lane(32)]
    {
        uint4* f1s = (uint4*)(sm + OFF_F1);
        for (int idx = tid; idx < 2048; idx += NTHR) {
            int nt = idx >> 7, rem = idx & 127;
            int s2 = rem >> 5, l = rem & 31;
            int q = l & 3, gp = l >> 2;
            int Ln = (gp >> 1) * 32 + 2 * nt + (gp & 1);
            int col = q * 16 + 4 * s2;
            float4 w = *(const float4*)(W_efeat + Ln * IN_DIM + col);
            f1s[idx] = make_uint4(cvt_tf32(w.x), cvt_tf32(w.y), cvt_tf32(w.z), cvt_tf32(w.w));
        }
    }
    // ---- stage W2 frags: [nt(16)][s2(8)][lane(32)]
    {
        uint4* f2s = (uint4*)(sm + OFF_F2);
        for (int idx = tid; idx < 4096; idx += NTHR) {
            int nt = idx >> 8, rem = idx & 255;
            int s2 = rem >> 5, l = rem & 31;
            int q = l & 3, gp = l >> 2;
            int n = nt * 8 + gp;
            int col = q * 32 + 4 * s2;
            float4 w = *(const float4*)(W_out + n * HID + col);
            f2s[idx] = make_uint4(cvt_tf32(w.x), cvt_tf32(w.y), cvt_tf32(w.z), cvt_tf32(w.w));
        }
    }
    if (tid < 128) {
        ((float*)(sm + OFF_BO))[tid] = b_out[tid];
        ((float*)(sm + OFF_GA))[tid] = gamma[tid];
        ((float*)(sm + OFF_BE))[tid] = beta[tid];
    }
    __syncthreads();

    const float* sBO = (const float*)(sm + OFF_BO);
    const float* sGA = (const float*)(sm + OFF_GA);
    const float* sBE = (const float*)(sm + OFF_BE);
    const uint4* f1 = (const uint4*)(sm + OFF_F1);
    const uint4* f2 = (const uint4*)(sm + OFF_F2);

    const int lane = tid & 31, warp = tid >> 5;
    const int qrow = lane >> 2, qcol = lane & 3;

    for (int tile = blockIdx.x; tile < ntiles; tile += gridDim.x) {
        const int e0w = tile * ETILE + warp * 16;
        const int er0i = e0w + qrow, er1i = er0i + 8;
        const int ge0 = (er0i < E) ? er0i : (E - 1);
        const int ge1 = (er1i < E) ? er1i : (E - 1);

        // gather pointers (each thread's span = 32 contiguous floats = one 128B line)
        const int si0 = src_idx[ge0], di0 = dst_idx[ge0];
        const int si1 = src_idx[ge1], di1 = dst_idx[ge1];
        const float4* ps0 = (const float4*)(g_src_proj + (size_t)si0 * HID + qcol * 32);
        const float4* pd0 = (const float4*)(g_dst_proj + (size_t)di0 * HID + qcol * 32);
        const float4* ps1 = (const float4*)(g_src_proj + (size_t)si1 * HID + qcol * 32);
        const float4* pd1 = (const float4*)(g_dst_proj + (size_t)di1 * HID + qcol * 32);
        asm volatile("prefetch.global.L2 [%0];" :: "l"(ps0));
        asm volatile("prefetch.global.L2 [%0];" :: "l"(pd0));
        asm volatile("prefetch.global.L2 [%0];" :: "l"(ps1));
        asm volatile("prefetch.global.L2 [%0];" :: "l"(pd1));

        // ---- A1 frags: 16 contiguous floats per row (psi permutation) ----
        uint32_t a1[8][4];
        {
            const float4* e0p = (const float4*)(efeat + (size_t)ge0 * IN_DIM + qcol * 16);
            const float4* e1p = (const float4*)(efeat + (size_t)ge1 * IN_DIM + qcol * 16);
            #pragma unroll
            for (int t = 0; t < 4; t++) {
                float4 v0 = e0p[t], v1 = e1p[t];
                a1[2*t][0]   = cvt_tf32(v0.x); a1[2*t][2]   = cvt_tf32(v0.y);
                a1[2*t][1]   = cvt_tf32(v1.x); a1[2*t][3]   = cvt_tf32(v1.y);
                a1[2*t+1][0] = cvt_tf32(v0.z); a1[2*t+1][2] = cvt_tf32(v0.w);
                a1[2*t+1][1] = cvt_tf32(v1.z); a1[2*t+1][3] = cvt_tf32(v1.w);
            }
        }

        // ---- GEMM1: 128x128x64 tf32 ----
        float acc1[16][4];
        #pragma unroll
        for (int j = 0; j < 16; j++) { acc1[j][0]=0.f; acc1[j][1]=0.f; acc1[j][2]=0.f; acc1[j][3]=0.f; }
        #pragma unroll
        for (int s2 = 0; s2 < 4; s2++) {
            #pragma unroll
            for (int ntg = 0; ntg < 4; ntg++) {
                const int n0 = 4 * ntg;
                uint4 b0 = f1[((n0 + 0) * 4 + s2) * 32 + lane];
                uint4 b1 = f1[((n0 + 1) * 4 + s2) * 32 + lane];
                uint4 b2 = f1[((n0 + 2) * 4 + s2) * 32 + lane];
                uint4 b3 = f1[((n0 + 3) * 4 + s2) * 32 + lane];
                mma_tf32(acc1[n0+0], a1[2*s2],   b0.x, b0.y);
                mma_tf32(acc1[n0+1], a1[2*s2],   b1.x, b1.y);
                mma_tf32(acc1[n0+2], a1[2*s2],   b2.x, b2.y);
                mma_tf32(acc1[n0+3], a1[2*s2],   b3.x, b3.y);
                mma_tf32(acc1[n0+0], a1[2*s2+1], b0.z, b0.w);
                mma_tf32(acc1[n0+1], a1[2*s2+1], b1.z, b1.w);
                mma_tf32(acc1[n0+2], a1[2*s2+1], b2.z, b2.w);
                mma_tf32(acc1[n0+3], a1[2*s2+1], b3.z, b3.w);
            }
        }

        // ---- gather + SiLU + cvt to GEMM2 A-frags ----
        uint32_t a2[16][4];
        #pragma unroll
        for (int ntp = 0; ntp < 8; ntp++) {
            float4 gs0 = ps0[ntp], gd0 = pd0[ntp];
            float4 gs1 = ps1[ntp], gd1 = pd1[ntp];
            {
                const int nt = 2 * ntp;
                float v0 = fsilu(acc1[nt][0] + gs0.x + gd0.x);
                float v1 = fsilu(acc1[nt][1] + gs0.y + gd0.y);
                float v2 = fsilu(acc1[nt][2] + gs1.x + gd1.x);
                float v3 = fsilu(acc1[nt][3] + gs1.y + gd1.y);
                a2[nt][0] = cvt_tf32(v0); a2[nt][2] = cvt_tf32(v1);
                a2[nt][1] = cvt_tf32(v2); a2[nt][3] = cvt_tf32(v3);
            }
            {
                const int nt = 2 * ntp + 1;
                float v0 = fsilu(acc1[nt][0] + gs0.z + gd0.z);
                float v1 = fsilu(acc1[nt][1] + gs0.w + gd0.w);
                float v2 = fsilu(acc1[nt][2] + gs1.z + gd1.z);
                float v3 = fsilu(acc1[nt][3] + gs1.w + gd1.w);
                a2[nt][0] = cvt_tf32(v0); a2[nt][2] = cvt_tf32(v1);
                a2[nt][1] = cvt_tf32(v2); a2[nt][3] = cvt_tf32(v3);
            }
        }

        // ---- GEMM2: 128x128x128 tf32 ----
        float acc2[16][4];
        #pragma unroll
        for (int j = 0; j < 16; j++) { acc2[j][0]=0.f; acc2[j][1]=0.f; acc2[j][2]=0.f; acc2[j][3]=0.f; }
        #pragma unroll
        for (int s2 = 0; s2 < 8; s2++) {
            #pragma unroll
            for (int ntg = 0; ntg < 4; ntg++) {
                const int n0 = 4 * ntg;
                uint4 b0 = f2[((n0 + 0) * 8 + s2) * 32 + lane];
                uint4 b1 = f2[((n0 + 1) * 8 + s2) * 32 + lane];
                uint4 b2 = f2[((n0 + 2) * 8 + s2) * 32 + lane];
                uint4 b3 = f2[((n0 + 3) * 8 + s2) * 32 + lane];
                mma_tf32(acc2[n0+0], a2[2*s2],   b0.x, b0.y);
                mma_tf32(acc2[n0+1], a2[2*s2],   b1.x, b1.y);
                mma_tf32(acc2[n0+2], a2[2*s2],   b2.x, b2.y);
                mma_tf32(acc2[n0+3], a2[2*s2],   b3.x, b3.y);
                mma_tf32(acc2[n0+0], a2[2*s2+1], b0.z, b0.w);
                mma_tf32(acc2[n0+1], a2[2*s2+1], b1.z, b1.w);
                mma_tf32(acc2[n0+2], a2[2*s2+1], b2.z, b2.w);
                mma_tf32(acc2[n0+3], a2[2*s2+1], b3.z, b3.w);
            }
        }

        // ---- bias + LayerNorm (quad shuffle) + store ----
        float s0 = 0.f, ss0 = 0.f, s1 = 0.f, ss1 = 0.f;
        #pragma unroll
        for (int j = 0; j < 16; j++) {
            float2 bo = *(const float2*)(sBO + 8 * j + 2 * qcol);
            acc2[j][0] += bo.x; acc2[j][1] += bo.y;
            acc2[j][2] += bo.x; acc2[j][3] += bo.y;
            s0  += acc2[j][0] + acc2[j][1];
            ss0 += acc2[j][0] * acc2[j][0] + acc2[j][1] * acc2[j][1];
            s1  += acc2[j][2] + acc2[j][3];
            ss1 += acc2[j][2] * acc2[j][2] + acc2[j][3] * acc2[j][3];
        }
        s0  += __shfl_xor_sync(0xffffffffu, s0, 1);  s0  += __shfl_xor_sync(0xffffffffu, s0, 2);
        ss0 += __shfl_xor_sync(0xffffffffu, ss0, 1); ss0 += __shfl_xor_sync(0xffffffffu, ss0, 2);
        s1  += __shfl_xor_sync(0xffffffffu, s1, 1);  s1  += __shfl_xor_sync(0xffffffffu, s1, 2);
        ss1 += __shfl_xor_sync(0xffffffffu, ss1, 1); ss1 += __shfl_xor_sync(0xffffffffu, ss1, 2);

        const float m0 = s0 * (1.0f / OUTD);
        const float v0 = ss0 * (1.0f / OUTD) - m0 * m0;
        const float i0 = rsqrtf(v0 + 1e-5f);
        const float m1 = s1 * (1.0f / OUTD);
        const float v1 = ss1 * (1.0f / OUTD) - m1 * m1;
        const float i1 = rsqrtf(v1 + 1e-5f);

        const bool st0 = (er0i < E), st1 = (er1i < E);
        float* o0 = out + (size_t)er0i * OUTD + 2 * qcol;
        float* o1 = out + (size_t)er1i * OUTD + 2 * qcol;
        #pragma unroll
        for (int j = 0; j < 16; j++) {
            float2 ga = *(const float2*)(sGA + 8 * j + 2 * qcol);
            float2 be = *(const float2*)(sBE + 8 * j + 2 * qcol);
            if (st0) {
                float2 w;
                w.x = (acc2[j][0] - m0) * i0 * ga.x + be.x;
                w.y = (acc2[j][1] - m0) * i0 * ga.y + be.y;
                *(float2*)(o0 + 8 * j) = w;
            }
            if (st1) {
                float2 w;
                w.x = (acc2[j][2] - m1) * i1 * ga.x + be.x;
                w.y = (acc2[j][3] - m1) * i1 * ga.y + be.y;
                *(float2*)(o1 + 8 * j) = w;
            }
        }
    }
}

// ---------------------------------------------------------------------------
extern "C" void kernel_launch(void* const* d_in, const int* in_sizes, int n_in,
                              void* d_out, int out_size)
{
    const float* efeat    = (const float*)d_in[0];
    const float* src_feat = (const float*)d_in[1];
    const float* dst_feat = (const float*)d_in[2];
    const int*   src_idx  = (const int*)d_in[3];
    const int*   dst_idx  = (const int*)d_in[4];
    const float* W_efeat  = (const float*)d_in[5];
    const float* W_src    = (const float*)d_in[6];
    const float* W_dst    = (const float*)d_in[7];
    const float* b1       = (const float*)d_in[8];
    const float* W_out    = (const float*)d_in[9];
    const float* b_out    = (const float*)d_in[10];
    const float* ln_gamma = (const float*)d_in[11];
    const float* ln_beta  = (const float*)d_in[12];
    float* out = (float*)d_out;

    const int E  = in_sizes[0] / IN_DIM;
    const int Nn = in_sizes[1] / IN_DIM;
    const int ntiles  = (E + ETILE - 1) / ETILE;
    const int ntilesN = (Nn + 127) / 128;

    cudaFuncSetAttribute(node_mma_kernel, cudaFuncAttributeMaxDynamicSharedMemorySize, SMEM_NODE_BYTES);
    cudaFuncSetAttribute(edge_tf32_kernel, cudaFuncAttributeMaxDynamicSharedMemorySize, SMEM_EDGE_BYTES);

    int nsm = 148;
    cudaDeviceGetAttribute(&nsm, cudaDevAttrMultiProcessorCount, 0);

    int gridN = 2 * ntilesN < nsm ? 2 * ntilesN : nsm;
    node_mma_kernel<<<gridN, 256, SMEM_NODE_BYTES>>>(src_feat, dst_feat, W_src, W_dst, b1, Nn, ntilesN);

    int grid = (ntiles < nsm) ? ntiles : nsm;
    edge_tf32_kernel<<<grid, NTHR, SMEM_EDGE_BYTES>>>(efeat, src_idx, dst_idx, W_efeat, W_out,
                                                      b_out, ln_gamma, ln_beta, out, E, ntiles);
}

// round 10
// speedup vs baseline: 1.4028x; 1.2087x over previous
#include <cuda_runtime.h>
#include <cuda_bf16.h>
#include <stdint.h>
#include <math.h>

#define IN_DIM 64
#define HID    128
#define OUTD   128
#define ETILE  192          // edges per CTA-tile (12 warps x 16)
#define NTHR   384
#define MAXN   100000

// ------------------------- scratch (no-alloc rule) --------------------------
__device__ float g_src_proj[(size_t)MAXN * HID];
__device__ float g_dst_proj[(size_t)MAXN * HID];

// ------------------------- helpers ------------------------------------------
__device__ __forceinline__ uint32_t smem_u32(const void* p) {
    uint32_t a;
    asm("{ .reg .u64 t; cvta.to.shared.u64 t, %1; cvt.u32.u64 %0, t; }" : "=r"(a) : "l"(p));
    return a;
}
__device__ __forceinline__ void ldsm4(uint32_t* r, uint32_t addr) {
    asm volatile("ldmatrix.sync.aligned.m8n8.x4.shared.b16 {%0,%1,%2,%3}, [%4];"
                 : "=r"(r[0]), "=r"(r[1]), "=r"(r[2]), "=r"(r[3]) : "r"(addr));
}
__device__ __forceinline__ void mma16816(float* d, const uint32_t* a, const uint32_t* b) {
    asm volatile("mma.sync.aligned.m16n8k16.row.col.f32.bf16.bf16.f32 "
                 "{%0,%1,%2,%3}, {%4,%5,%6,%7}, {%8,%9}, {%0,%1,%2,%3};"
                 : "+f"(d[0]), "+f"(d[1]), "+f"(d[2]), "+f"(d[3])
                 : "r"(a[0]), "r"(a[1]), "r"(a[2]), "r"(a[3]), "r"(b[0]), "r"(b[1]));
}
__device__ __forceinline__ void mma_f16(float* d, const uint32_t* a, uint32_t b0, uint32_t b1) {
    asm volatile("mma.sync.aligned.m16n8k16.row.col.f32.f16.f16.f32 "
                 "{%0,%1,%2,%3}, {%4,%5,%6,%7}, {%8,%9}, {%0,%1,%2,%3};"
                 : "+f"(d[0]), "+f"(d[1]), "+f"(d[2]), "+f"(d[3])
                 : "r"(a[0]), "r"(a[1]), "r"(a[2]), "r"(a[3]), "r"(b0), "r"(b1));
}
// pack (x -> low half, y -> high half) as f16x2
__device__ __forceinline__ uint32_t h2pack(float x, float y) {
    uint32_t r;
    asm("cvt.rn.f16x2.f32 %0, %1, %2;" : "=r"(r) : "f"(y), "f"(x));
    return r;
}
__device__ __forceinline__ void split_pack(float x, float y, uint32_t& h, uint32_t& l) {
    __nv_bfloat16 xh = __float2bfloat16(x), yh = __float2bfloat16(y);
    __nv_bfloat16 xl = __float2bfloat16(x - __bfloat162float(xh));
    __nv_bfloat16 yl = __float2bfloat16(y - __bfloat162float(yh));
    h = (uint32_t)(*(uint16_t*)&xh) | ((uint32_t)(*(uint16_t*)&yh) << 16);
    l = (uint32_t)(*(uint16_t*)&xl) | ((uint32_t)(*(uint16_t*)&yl) << 16);
}
__device__ __forceinline__ float fsilu(float x) { return x / (1.0f + __expf(-x)); }

// ------------------------- smem layouts --------------------------------------
// edge kernel: W frags in fp16 frag-stream layout
#define OFF_F1 0          // 1024 uint4 = 16384 B : [j(16)][s2(2)][lane(32)]
#define OFF_F2 16384      // 2048 uint4 = 32768 B : [j(16)][s2(4)][lane(32)]
#define OFF_BO 49152
#define OFF_GA 49664
#define OFF_BE 50176
#define SMEM_EDGE_BYTES 50688
// node kernel (bf16 3-term)
#define W1_STRIDE 72
#define OFF_NSH 0
#define OFF_NSL 18432
#define OFF_NDH 36864
#define OFF_NDL 55296
#define OFF_NB1 73728
#define SMEM_NODE_BYTES 74240

__device__ __forceinline__ void stage_w64(const float* __restrict__ W,
                                          __nv_bfloat16* sH, __nv_bfloat16* sL, int tid, int nthr) {
    for (int i = tid; i < HID * (IN_DIM / 2); i += nthr) {
        int n = i >> 5, p = i & 31;
        float2 f = ((const float2*)W)[n * 32 + p];
        __nv_bfloat16 xh = __float2bfloat16(f.x), yh = __float2bfloat16(f.y);
        sH[n * W1_STRIDE + 2 * p]     = xh;
        sH[n * W1_STRIDE + 2 * p + 1] = yh;
        sL[n * W1_STRIDE + 2 * p]     = __float2bfloat16(f.x - __bfloat162float(xh));
        sL[n * W1_STRIDE + 2 * p + 1] = __float2bfloat16(f.y - __bfloat162float(yh));
    }
}

// ---------------------------------------------------------------------------
// Kernel 1: node projections via HMMA bf16 3-term (near-exact) — unchanged
// ---------------------------------------------------------------------------
__global__ __launch_bounds__(256) void node_mma_kernel(
    const float* __restrict__ src_feat, const float* __restrict__ dst_feat,
    const float* __restrict__ W_src, const float* __restrict__ W_dst,
    const float* __restrict__ b1, int Nn, int ntilesN)
{
    extern __shared__ char smraw[];
    char* sm = smraw;
    const uint32_t base = smem_u32(smraw);
    const int tid = threadIdx.x;

    stage_w64(W_src, (__nv_bfloat16*)(sm + OFF_NSH), (__nv_bfloat16*)(sm + OFF_NSL), tid, 256);
    stage_w64(W_dst, (__nv_bfloat16*)(sm + OFF_NDH), (__nv_bfloat16*)(sm + OFF_NDL), tid, 256);
    if (tid < 128) ((float*)(sm + OFF_NB1))[tid] = b1[tid];
    __syncthreads();

    const int lane = tid & 31, warp = tid >> 5;
    const int qrow = lane >> 2, qcol = lane & 3;
    const int g = lane >> 3, r = lane & 7;
    const int lro = ((g & 2) ? 8 : 0) + r;
    const int lco = (g & 1) * 8;
    const uint32_t lmoff = (uint32_t)(lro * W1_STRIDE + lco) * 2;

    const int nitems = 2 * ntilesN;
    for (int item = blockIdx.x; item < nitems; item += gridDim.x) {
        const bool is_dst = (item >= ntilesN);
        const int tile = is_dst ? (item - ntilesN) : item;
        const float* X = is_dst ? dst_feat : src_feat;
        float* Out = is_dst ? g_dst_proj : g_src_proj;
        const uint32_t wh_base = base + (is_dst ? OFF_NDH : OFF_NSH) + lmoff;
        const uint32_t wl_base = base + (is_dst ? OFF_NDL : OFF_NSL) + lmoff;

        const int n0w = tile * 128 + warp * 16;
        const int nr0i = n0w + qrow, nr1i = nr0i + 8;
        const int gn0 = (nr0i < Nn) ? nr0i : (Nn - 1);
        const int gn1 = (nr1i < Nn) ? nr1i : (Nn - 1);
        const float* xr0 = X + (size_t)gn0 * IN_DIM + 2 * qcol;
        const float* xr1 = X + (size_t)gn1 * IN_DIM + 2 * qcol;

        uint32_t aH[4][4], aL[4][4];
        #pragma unroll
        for (int s = 0; s < 4; s++) {
            float2 f0 = *(const float2*)(xr0 + 16 * s);
            float2 f1 = *(const float2*)(xr1 + 16 * s);
            float2 f2 = *(const float2*)(xr0 + 16 * s + 8);
            float2 f3 = *(const float2*)(xr1 + 16 * s + 8);
            split_pack(f0.x, f0.y, aH[s][0], aL[s][0]);
            split_pack(f1.x, f1.y, aH[s][1], aL[s][1]);
            split_pack(f2.x, f2.y, aH[s][2], aL[s][2]);
            split_pack(f3.x, f3.y, aH[s][3], aL[s][3]);
        }

        float acc[16][4];
        #pragma unroll
        for (int j = 0; j < 16; j++) { acc[j][0]=0.f; acc[j][1]=0.f; acc[j][2]=0.f; acc[j][3]=0.f; }

        #pragma unroll
        for (int s = 0; s < 4; s++) {
            uint32_t bH[8][4], bL[8][4];
            #pragma unroll
            for (int jp = 0; jp < 8; jp++)
                ldsm4(bH[jp], wh_base + (uint32_t)(jp * 16 * W1_STRIDE + 16 * s) * 2);
            #pragma unroll
            for (int jp = 0; jp < 8; jp++) {
                mma16816(acc[2*jp],   aH[s], bH[jp]);
                mma16816(acc[2*jp+1], aH[s], bH[jp] + 2);
            }
            #pragma unroll
            for (int jp = 0; jp < 8; jp++)
                ldsm4(bL[jp], wl_base + (uint32_t)(jp * 16 * W1_STRIDE + 16 * s) * 2);
            #pragma unroll
            for (int jp = 0; jp < 8; jp++) {
                mma16816(acc[2*jp],   aL[s], bH[jp]);
                mma16816(acc[2*jp+1], aL[s], bH[jp] + 2);
            }
            #pragma unroll
            for (int jp = 0; jp < 8; jp++) {
                mma16816(acc[2*jp],   aH[s], bL[jp]);
                mma16816(acc[2*jp+1], aH[s], bL[jp] + 2);
            }
        }

        const float* sb1 = (const float*)(sm + OFF_NB1);
        const bool st0 = (nr0i < Nn), st1 = (nr1i < Nn);
        float* o0 = Out + (size_t)nr0i * HID + 2 * qcol;
        float* o1 = Out + (size_t)nr1i * HID + 2 * qcol;
        #pragma unroll
        for (int j = 0; j < 16; j++) {
            float2 bb = make_float2(0.f, 0.f);
            if (is_dst) bb = *(const float2*)(sb1 + 8 * j + 2 * qcol);
            if (st0) *(float2*)(o0 + 8 * j) = make_float2(acc[j][0] + bb.x, acc[j][1] + bb.y);
            if (st1) *(float2*)(o1 + 8 * j) = make_float2(acc[j][2] + bb.x, acc[j][3] + bb.y);
        }
    }
}

// ---------------------------------------------------------------------------
// Kernel 2: persistent FP16 (m16n8k16) edge pipeline, frag-stream weights.
//   efeat perm: slice s of thread q covers true cols 16q + 4s + {0..3}
//   h perm:     thread q holds true h-cols 32q..32q+31; slice s -> 4s + {0..3}
// ---------------------------------------------------------------------------
__global__ __launch_bounds__(NTHR, 1) void edge_f16_kernel(
    const float* __restrict__ efeat,
    const int* __restrict__ src_idx, const int* __restrict__ dst_idx,
    const float* __restrict__ W_efeat, const float* __restrict__ W_out,
    const float* __restrict__ b_out, const float* __restrict__ gamma,
    const float* __restrict__ beta,
    float* __restrict__ out, int E, int ntiles)
{
    extern __shared__ char smraw[];
    char* sm = smraw;
    const int tid = threadIdx.x;

    // ---- stage W1 frags: [j(16)][s2(2)][lane(32)] uint4 = slices 2s2,2s2+1 (b0,b1 each)
    {
        uint4* f1s = (uint4*)(sm + OFF_F1);
        for (int idx = tid; idx < 1024; idx += NTHR) {
            int j = idx >> 6, rem = idx & 63;
            int s2 = rem >> 5, l = rem & 31;
            int q = l & 3, rho = l >> 2;
            int L = ((rho >> 1) << 5) + 2 * j + (rho & 1);   // true W1 row at this D position
            const float* wr = W_efeat + L * IN_DIM + q * 16 + s2 * 8;
            float4 wa = *(const float4*)wr;
            float4 wb = *(const float4*)(wr + 4);
            f1s[idx] = make_uint4(h2pack(wa.x, wa.y), h2pack(wa.z, wa.w),
                                  h2pack(wb.x, wb.y), h2pack(wb.z, wb.w));
        }
    }
    // ---- stage W2 frags: [j(16)][s2(4)][lane(32)]
    {
        uint4* f2s = (uint4*)(sm + OFF_F2);
        for (int idx = tid; idx < 2048; idx += NTHR) {
            int j = idx >> 7, rem = idx & 127;
            int s2 = rem >> 5, l = rem & 31;
            int q = l & 3, rho = l >> 2;
            int n = 8 * j + rho;                              // output n (unpermuted)
            const float* wr = W_out + n * HID + q * 32 + s2 * 8;
            float4 wa = *(const float4*)wr;
            float4 wb = *(const float4*)(wr + 4);
            f2s[idx] = make_uint4(h2pack(wa.x, wa.y), h2pack(wa.z, wa.w),
                                  h2pack(wb.x, wb.y), h2pack(wb.z, wb.w));
        }
    }
    if (tid < 128) {
        ((float*)(sm + OFF_BO))[tid] = b_out[tid];
        ((float*)(sm + OFF_GA))[tid] = gamma[tid];
        ((float*)(sm + OFF_BE))[tid] = beta[tid];
    }
    __syncthreads();

    const float* sBO = (const float*)(sm + OFF_BO);
    const float* sGA = (const float*)(sm + OFF_GA);
    const float* sBE = (const float*)(sm + OFF_BE);
    const uint4* f1 = (const uint4*)(sm + OFF_F1);
    const uint4* f2 = (const uint4*)(sm + OFF_F2);

    const int lane = tid & 31, warp = tid >> 5;
    const int qrow = lane >> 2, qcol = lane & 3;

    for (int tile = blockIdx.x; tile < ntiles; tile += gridDim.x) {
        const int e0w = tile * ETILE + warp * 16;
        const int er0i = e0w + qrow, er1i = er0i + 8;
        const int ge0 = (er0i < E) ? er0i : (E - 1);
        const int ge1 = (er1i < E) ? er1i : (E - 1);

        const int si0 = src_idx[ge0], di0 = dst_idx[ge0];
        const int si1 = src_idx[ge1], di1 = dst_idx[ge1];
        const float4* ps0 = (const float4*)(g_src_proj + (size_t)si0 * HID + qcol * 32);
        const float4* pd0 = (const float4*)(g_dst_proj + (size_t)di0 * HID + qcol * 32);
        const float4* ps1 = (const float4*)(g_src_proj + (size_t)si1 * HID + qcol * 32);
        const float4* pd1 = (const float4*)(g_dst_proj + (size_t)di1 * HID + qcol * 32);
        asm volatile("prefetch.global.L2 [%0];" :: "l"(ps0));
        asm volatile("prefetch.global.L2 [%0];" :: "l"(pd0));
        asm volatile("prefetch.global.L2 [%0];" :: "l"(ps1));
        asm volatile("prefetch.global.L2 [%0];" :: "l"(pd1));

        // ---- A1 fragments (fp16): 16 contiguous floats per row per thread ----
        uint32_t a1f[4][4];
        {
            const float4* e0p = (const float4*)(efeat + (size_t)ge0 * IN_DIM + qcol * 16);
            const float4* e1p = (const float4*)(efeat + (size_t)ge1 * IN_DIM + qcol * 16);
            #pragma unroll
            for (int s = 0; s < 4; s++) {
                float4 v0 = e0p[s], v1 = e1p[s];
                a1f[s][0] = h2pack(v0.x, v0.y);
                a1f[s][1] = h2pack(v1.x, v1.y);
                a1f[s][2] = h2pack(v0.z, v0.w);
                a1f[s][3] = h2pack(v1.z, v1.w);
            }
        }

        // ---- GEMM1: 16x128x64 per warp, fp16 k16 ----
        float acc1[16][4];
        #pragma unroll
        for (int j = 0; j < 16; j++) { acc1[j][0]=0.f; acc1[j][1]=0.f; acc1[j][2]=0.f; acc1[j][3]=0.f; }
        #pragma unroll
        for (int s2 = 0; s2 < 2; s2++) {
            #pragma unroll
            for (int jg = 0; jg < 4; jg++) {
                const int n0 = 4 * jg;
                uint4 b0 = f1[((n0 + 0) * 2 + s2) * 32 + lane];
                uint4 b1 = f1[((n0 + 1) * 2 + s2) * 32 + lane];
                uint4 b2 = f1[((n0 + 2) * 2 + s2) * 32 + lane];
                uint4 b3 = f1[((n0 + 3) * 2 + s2) * 32 + lane];
                mma_f16(acc1[n0+0], a1f[2*s2],   b0.x, b0.y);
                mma_f16(acc1[n0+1], a1f[2*s2],   b1.x, b1.y);
                mma_f16(acc1[n0+2], a1f[2*s2],   b2.x, b2.y);
                mma_f16(acc1[n0+3], a1f[2*s2],   b3.x, b3.y);
                mma_f16(acc1[n0+0], a1f[2*s2+1], b0.z, b0.w);
                mma_f16(acc1[n0+1], a1f[2*s2+1], b1.z, b1.w);
                mma_f16(acc1[n0+2], a1f[2*s2+1], b2.z, b2.w);
                mma_f16(acc1[n0+3], a1f[2*s2+1], b3.z, b3.w);
            }
        }

        // ---- gather + SiLU + pack GEMM2 A-frags (fp16) ----
        uint32_t a2f[8][4];
        #pragma unroll
        for (int s = 0; s < 8; s++) {
            float4 gs0 = ps0[s], gd0 = pd0[s];
            float4 gs1 = ps1[s], gd1 = pd1[s];
            float u0 = fsilu(acc1[2*s][0]   + gs0.x + gd0.x);   // row0, col 4s+0
            float u1 = fsilu(acc1[2*s][1]   + gs0.y + gd0.y);   // row0, col 4s+1
            float u2 = fsilu(acc1[2*s+1][0] + gs0.z + gd0.z);   // row0, col 4s+2
            float u3 = fsilu(acc1[2*s+1][1] + gs0.w + gd0.w);   // row0, col 4s+3
            float w0 = fsilu(acc1[2*s][2]   + gs1.x + gd1.x);   // row1, col 4s+0
            float w1 = fsilu(acc1[2*s][3]   + gs1.y + gd1.y);
            float w2 = fsilu(acc1[2*s+1][2] + gs1.z + gd1.z);
            float w3 = fsilu(acc1[2*s+1][3] + gs1.w + gd1.w);
            a2f[s][0] = h2pack(u0, u1);
            a2f[s][1] = h2pack(w0, w1);
            a2f[s][2] = h2pack(u2, u3);
            a2f[s][3] = h2pack(w2, w3);
        }

        // ---- GEMM2: 16x128x128 per warp, fp16 k16 ----
        float acc2[16][4];
        #pragma unroll
        for (int j = 0; j < 16; j++) { acc2[j][0]=0.f; acc2[j][1]=0.f; acc2[j][2]=0.f; acc2[j][3]=0.f; }
        #pragma unroll
        for (int s2 = 0; s2 < 4; s2++) {
            #pragma unroll
            for (int jg = 0; jg < 4; jg++) {
                const int n0 = 4 * jg;
                uint4 b0 = f2[((n0 + 0) * 4 + s2) * 32 + lane];
                uint4 b1 = f2[((n0 + 1) * 4 + s2) * 32 + lane];
                uint4 b2 = f2[((n0 + 2) * 4 + s2) * 32 + lane];
                uint4 b3 = f2[((n0 + 3) * 4 + s2) * 32 + lane];
                mma_f16(acc2[n0+0], a2f[2*s2],   b0.x, b0.y);
                mma_f16(acc2[n0+1], a2f[2*s2],   b1.x, b1.y);
                mma_f16(acc2[n0+2], a2f[2*s2],   b2.x, b2.y);
                mma_f16(acc2[n0+3], a2f[2*s2],   b3.x, b3.y);
                mma_f16(acc2[n0+0], a2f[2*s2+1], b0.z, b0.w);
                mma_f16(acc2[n0+1], a2f[2*s2+1], b1.z, b1.w);
                mma_f16(acc2[n0+2], a2f[2*s2+1], b2.z, b2.w);
                mma_f16(acc2[n0+3], a2f[2*s2+1], b3.z, b3.w);
            }
        }

        // ---- bias + LayerNorm (quad shuffle) + store ----
        float s0 = 0.f, ss0 = 0.f, s1 = 0.f, ss1 = 0.f;
        #pragma unroll
        for (int j = 0; j < 16; j++) {
            float2 bo = *(const float2*)(sBO + 8 * j + 2 * qcol);
            acc2[j][0] += bo.x; acc2[j][1] += bo.y;
            acc2[j][2] += bo.x; acc2[j][3] += bo.y;
            s0  += acc2[j][0] + acc2[j][1];
            ss0 += acc2[j][0] * acc2[j][0] + acc2[j][1] * acc2[j][1];
            s1  += acc2[j][2] + acc2[j][3];
            ss1 += acc2[j][2] * acc2[j][2] + acc2[j][3] * acc2[j][3];
        }
        s0  += __shfl_xor_sync(0xffffffffu, s0, 1);  s0  += __shfl_xor_sync(0xffffffffu, s0, 2);
        ss0 += __shfl_xor_sync(0xffffffffu, ss0, 1); ss0 += __shfl_xor_sync(0xffffffffu, ss0, 2);
        s1  += __shfl_xor_sync(0xffffffffu, s1, 1);  s1  += __shfl_xor_sync(0xffffffffu, s1, 2);
        ss1 += __shfl_xor_sync(0xffffffffu, ss1, 1); ss1 += __shfl_xor_sync(0xffffffffu, ss1, 2);

        const float m0 = s0 * (1.0f / OUTD);
        const float v0 = ss0 * (1.0f / OUTD) - m0 * m0;
        const float i0 = rsqrtf(v0 + 1e-5f);
        const float m1 = s1 * (1.0f / OUTD);
        const float v1 = ss1 * (1.0f / OUTD) - m1 * m1;
        const float i1 = rsqrtf(v1 + 1e-5f);

        const bool st0 = (er0i < E), st1 = (er1i < E);
        float* o0 = out + (size_t)er0i * OUTD + 2 * qcol;
        float* o1 = out + (size_t)er1i * OUTD + 2 * qcol;
        #pragma unroll
        for (int j = 0; j < 16; j++) {
            float2 ga = *(const float2*)(sGA + 8 * j + 2 * qcol);
            float2 be = *(const float2*)(sBE + 8 * j + 2 * qcol);
            if (st0) {
                float2 w;
                w.x = (acc2[j][0] - m0) * i0 * ga.x + be.x;
                w.y = (acc2[j][1] - m0) * i0 * ga.y + be.y;
                *(float2*)(o0 + 8 * j) = w;
            }
            if (st1) {
                float2 w;
                w.x = (acc2[j][2] - m1) * i1 * ga.x + be.x;
                w.y = (acc2[j][3] - m1) * i1 * ga.y + be.y;
                *(float2*)(o1 + 8 * j) = w;
            }
        }
    }
}

// ---------------------------------------------------------------------------
extern "C" void kernel_launch(void* const* d_in, const int* in_sizes, int n_in,
                              void* d_out, int out_size)
{
    const float* efeat    = (const float*)d_in[0];
    const float* src_feat = (const float*)d_in[1];
    const float* dst_feat = (const float*)d_in[2];
    const int*   src_idx  = (const int*)d_in[3];
    const int*   dst_idx  = (const int*)d_in[4];
    const float* W_efeat  = (const float*)d_in[5];
    const float* W_src    = (const float*)d_in[6];
    const float* W_dst    = (const float*)d_in[7];
    const float* b1       = (const float*)d_in[8];
    const float* W_out    = (const float*)d_in[9];
    const float* b_out    = (const float*)d_in[10];
    const float* ln_gamma = (const float*)d_in[11];
    const float* ln_beta  = (const float*)d_in[12];
    float* out = (float*)d_out;

    const int E  = in_sizes[0] / IN_DIM;
    const int Nn = in_sizes[1] / IN_DIM;
    const int ntiles  = (E + ETILE - 1) / ETILE;
    const int ntilesN = (Nn + 127) / 128;

    cudaFuncSetAttribute(node_mma_kernel, cudaFuncAttributeMaxDynamicSharedMemorySize, SMEM_NODE_BYTES);
    cudaFuncSetAttribute(edge_f16_kernel, cudaFuncAttributeMaxDynamicSharedMemorySize, SMEM_EDGE_BYTES);

    int nsm = 148;
    cudaDeviceGetAttribute(&nsm, cudaDevAttrMultiProcessorCount, 0);

    int gridN = 2 * ntilesN < nsm ? 2 * ntilesN : nsm;
    node_mma_kernel<<<gridN, 256, SMEM_NODE_BYTES>>>(src_feat, dst_feat, W_src, W_dst, b1, Nn, ntilesN);

    int grid = (ntiles < nsm) ? ntiles : nsm;
    edge_f16_kernel<<<grid, NTHR, SMEM_EDGE_BYTES>>>(efeat, src_idx, dst_idx, W_efeat, W_out,
                                                     b_out, ln_gamma, ln_beta, out, E, ntiles);
}